// round 4
// baseline (speedup 1.0000x reference)
#include <cuda_runtime.h>
#include <cuda_bf16.h>

// Collapse v2:
//   out[b, v] = cnt_b[v] * exp(R[q_b, v]) / sum_w cnt_b[w] * exp(R[q_b, w])
// where q_b = tok[b, N-1] and cnt_b is the histogram of tok[b, :].
// Softmax is shift-invariant and |R| ~ 2.4e-4, so no max subtraction needed.

#define B 16
#define N 1024
#define V 4096

__global__ __launch_bounds__(N, 1)
void last_row_attn_kernel(const int* __restrict__ tok,
                          const float* __restrict__ R,
                          float* __restrict__ out) {
    __shared__ int   cnt[V];        // token histogram (16 KB)
    __shared__ float red_sum[32];

    const int b   = blockIdx.x;
    const int tid = threadIdx.x;
    const int* t  = tok + b * N;

    // Issue the two independent global loads immediately.
    const int q  = __ldg(t + (N - 1));   // last-row query token
    const int tm = __ldg(t + tid);       // this thread's key token

    // R row load depends only on q -> compiler can issue it before the
    // histogram barrier, overlapping its latency with the atomic phase.
    const float4 r4 = *reinterpret_cast<const float4*>(
        R + (size_t)q * V + (size_t)tid * 4);

    // zero histogram (4 ints per thread, int4-pattern addresses)
    cnt[tid]        = 0;
    cnt[tid + 1024] = 0;
    cnt[tid + 2048] = 0;
    cnt[tid + 3072] = 0;
    __syncthreads();

    atomicAdd(&cnt[tm], 1);
    __syncthreads();

    // counts for this thread's 4 vocab slots (int4 -> conflict-free LDS.128)
    const int4 c4 = *reinterpret_cast<const int4*>(&cnt[tid * 4]);

    const float e0 = (float)c4.x * __expf(r4.x);
    const float e1 = (float)c4.y * __expf(r4.y);
    const float e2 = (float)c4.z * __expf(r4.z);
    const float e3 = (float)c4.w * __expf(r4.w);

    // ---- block sum ----
    float s = (e0 + e1) + (e2 + e3);
    #pragma unroll
    for (int o = 16; o > 0; o >>= 1)
        s += __shfl_xor_sync(0xffffffffu, s, o);
    if ((tid & 31) == 0) red_sum[tid >> 5] = s;
    __syncthreads();
    if (tid < 32) {
        float v = red_sum[tid];
        #pragma unroll
        for (int o = 16; o > 0; o >>= 1)
            v += __shfl_xor_sync(0xffffffffu, v, o);
        red_sum[tid] = v;
    }
    __syncthreads();
    const float inv = 1.0f / red_sum[0];

    // ---- coalesced vectorized write-out ----
    float4 o4;
    o4.x = e0 * inv;
    o4.y = e1 * inv;
    o4.z = e2 * inv;
    o4.w = e3 * inv;
    *reinterpret_cast<float4*>(out + (size_t)b * V + (size_t)tid * 4) = o4;
}

extern "C" void kernel_launch(void* const* d_in, const int* in_sizes, int n_in,
                              void* d_out, int out_size) {
    const int*   tok = (const int*)d_in[0];     // (16, 1024) int32
    const float* R   = (const float*)d_in[1];   // (4096, 4096) float32
    float*       out = (float*)d_out;           // (16, 4096) float32
    last_row_attn_kernel<<<B, N>>>(tok, R, out);
}

// round 5
// speedup vs baseline: 1.0386x; 1.0386x over previous
#include <cuda_runtime.h>
#include <cuda_bf16.h>

// out[b, v] = cnt_b[v] * exp(R[q_b, v]) / sum_w cnt_b[w] * exp(R[q_b, w])
// q_b = tok[b, N-1]; cnt_b = histogram of tok[b, :].
// |R| ~ 2.4e-4 so exp never overflows -> no max-subtraction pass.
//
// 16 CTAs (one per batch) x 512 threads; 8 vocab slots per thread.

#define B 16
#define N 1024
#define V 4096
#define T 512   // threads per CTA

__global__ __launch_bounds__(T, 1)
void last_row_attn_kernel(const int* __restrict__ tok,
                          const float* __restrict__ R,
                          float* __restrict__ out) {
    __shared__ int   cnt[V];          // token histogram (16 KB)
    __shared__ float red_sum[16];     // one partial per warp

    const int b    = blockIdx.x;
    const int tid  = threadIdx.x;
    const int lane = tid & 31;
    const int wid  = tid >> 5;
    const int* t   = tok + b * N;

    // Independent global loads first.
    const int q   = __ldg(t + (N - 1));     // last-row query token
    const int tm0 = __ldg(t + tid);
    const int tm1 = __ldg(t + tid + T);

    // R row (depends only on q): 2 x float4 per thread, coalesced.
    const float4* Rq = reinterpret_cast<const float4*>(R + (size_t)q * V);
    const float4 ra = Rq[tid * 2];
    const float4 rb = Rq[tid * 2 + 1];

    // Vectorized zero of histogram: 1024 int4 slots, 2 per thread.
    int4* cnt4 = reinterpret_cast<int4*>(cnt);
    const int4 z = make_int4(0, 0, 0, 0);
    cnt4[tid]     = z;
    cnt4[tid + T] = z;
    __syncthreads();                        // bar1: zero -> atomics

    atomicAdd(&cnt[tm0], 1);
    atomicAdd(&cnt[tm1], 1);

    // exp of R row overlaps atomic drain (independent of histogram).
    const float xa0 = __expf(ra.x), xa1 = __expf(ra.y);
    const float xa2 = __expf(ra.z), xa3 = __expf(ra.w);
    const float xb0 = __expf(rb.x), xb1 = __expf(rb.y);
    const float xb2 = __expf(rb.z), xb3 = __expf(rb.w);
    __syncthreads();                        // bar2: atomics -> read

    const int4 ca = cnt4[tid * 2];
    const int4 cb = cnt4[tid * 2 + 1];

    const float e0 = (float)ca.x * xa0;
    const float e1 = (float)ca.y * xa1;
    const float e2 = (float)ca.z * xa2;
    const float e3 = (float)ca.w * xa3;
    const float e4 = (float)cb.x * xb0;
    const float e5 = (float)cb.y * xb1;
    const float e6 = (float)cb.z * xb2;
    const float e7 = (float)cb.w * xb3;

    // ---- block sum: warp shfl-reduce, then every warp reduces the 16
    // partials redundantly (no second barrier, no warp0-only stage). ----
    float s = ((e0 + e1) + (e2 + e3)) + ((e4 + e5) + (e6 + e7));
    #pragma unroll
    for (int o = 16; o > 0; o >>= 1)
        s += __shfl_xor_sync(0xffffffffu, s, o);
    if (lane == 0) red_sum[wid] = s;
    __syncthreads();                        // bar3: partials -> read

    float v = red_sum[lane & 15];           // each entry read by 2 lanes (bcast)
    #pragma unroll
    for (int o = 8; o > 0; o >>= 1)
        v += __shfl_xor_sync(0xffffffffu, v, o);
    const float inv = 1.0f / v;

    // ---- coalesced vectorized write-out: 2 x float4 per thread ----
    float4* o4 = reinterpret_cast<float4*>(out + (size_t)b * V);
    float4 oa, ob;
    oa.x = e0 * inv; oa.y = e1 * inv; oa.z = e2 * inv; oa.w = e3 * inv;
    ob.x = e4 * inv; ob.y = e5 * inv; ob.z = e6 * inv; ob.w = e7 * inv;
    o4[tid * 2]     = oa;
    o4[tid * 2 + 1] = ob;
}

extern "C" void kernel_launch(void* const* d_in, const int* in_sizes, int n_in,
                              void* d_out, int out_size) {
    const int*   tok = (const int*)d_in[0];     // (16, 1024) int32
    const float* R   = (const float*)d_in[1];   // (4096, 4096) float32
    float*       out = (float*)d_out;           // (16, 4096) float32
    last_row_attn_kernel<<<B, T>>>(tok, R, out);
}